// round 10
// baseline (speedup 1.0000x reference)
#include <cuda_runtime.h>
#include <math.h>

// Problem dims (fixed by the reference)
#define BATCH 16
#define NQ    500   // queries (pred) = columns
#define NT    128   // targets       = rows
#define KPT   34    // 17 keypoints * 2
#define NCPL  16    // columns per lane: ceil(500/32)

// Transposed cost scratch: [b][target n][query q]
__device__ float  g_ct [BATCH * NT * NQ];   // f32 (exact row reduction)
__device__ double g_dct[BATCH * NT * NQ];   // f64 (path search)

// ---------------------------------------------------------------------------
// Kernel 1: cost matrix. One block per (b, q), 128 threads = one per target n.
// ---------------------------------------------------------------------------
__global__ __launch_bounds__(128) void cost_kernel(
    const float* __restrict__ pred_boxes,   // (B, Q, 4)  cxcywh
    const float* __restrict__ pred_kpts,    // (B, Q, 17, 2)
    const float* __restrict__ tgt_boxes,    // (B, N, 4)  cxcywh
    const float* __restrict__ tgt_kpts,     // (B, N, 17, 2)
    float* __restrict__ C)                  // (B, Q, N)
{
    const int q = blockIdx.x;
    const int b = blockIdx.y;
    const int n = threadIdx.x;

    __shared__ float s_pk[KPT];
    __shared__ float s_pb[4];
    const float* pbq = pred_boxes + (b * NQ + q) * 4;
    const float* pkq = pred_kpts + (size_t)(b * NQ + q) * KPT;
    if (n < KPT) s_pk[n] = pkq[n];
    if (n < 4)   s_pb[n] = pbq[n];
    __syncthreads();

    const float* tbn = tgt_boxes + (b * NT + n) * 4;
    const float* tkn = tgt_kpts + (size_t)(b * NT + n) * KPT;

    const float p0 = s_pb[0], p1 = s_pb[1], p2 = s_pb[2], p3 = s_pb[3];
    const float t0 = tbn[0], t1 = tbn[1], t2 = tbn[2], t3 = tbn[3];

    float cbbox = fabsf(p0 - t0) + fabsf(p1 - t1) + fabsf(p2 - t2) + fabsf(p3 - t3);

    float px0 = p0 - 0.5f * p2, py0 = p1 - 0.5f * p3;
    float px1 = p0 + 0.5f * p2, py1 = p1 + 0.5f * p3;
    px1 = fmaxf(px1, px0 + 1e-4f);
    py1 = fmaxf(py1, py0 + 1e-4f);
    float tx0 = t0 - 0.5f * t2, ty0 = t1 - 0.5f * t3;
    float tx1 = t0 + 0.5f * t2, ty1 = t1 + 0.5f * t3;
    tx1 = fmaxf(tx1, tx0 + 1e-4f);
    ty1 = fmaxf(ty1, ty0 + 1e-4f);

    const float ap = (px1 - px0) * (py1 - py0);
    const float at = (tx1 - tx0) * (ty1 - ty0);

    const float iw = fmaxf(fminf(px1, tx1) - fmaxf(px0, tx0), 0.0f);
    const float ih = fmaxf(fminf(py1, ty1) - fmaxf(py0, ty0), 0.0f);
    const float inter = iw * ih;
    const float uni = ap + at - inter;
    const float iou = inter / uni;

    const float ew = fmaxf(fmaxf(px1, tx1) - fminf(px0, tx0), 0.0f);
    const float eh = fmaxf(fmaxf(py1, ty1) - fminf(py0, ty0), 0.0f);
    const float enc = ew * eh;
    const float giou = iou - (enc - uni) / enc;

    float ckpt = 0.0f;
#pragma unroll
    for (int k = 0; k < KPT; k++) ckpt += fabsf(s_pk[k] - tkn[k]);

    const float cost = 5.0f * cbbox - 2.0f * giou + 1.0f * ckpt;

    C[(size_t)(b * NQ + q) * NT + n] = cost;
    const size_t ti = (size_t)(b * NT + n) * NQ + q;
    g_ct[ti]  = cost;
    g_dct[ti] = (double)cost;
}

// Monotone bijection double <-> uint64 (order-preserving, exact).
__device__ __forceinline__ unsigned long long dkey(double x) {
    const long long b = __double_as_longlong(x);
    return (unsigned long long)b ^ ((b < 0) ? 0xFFFFFFFFFFFFFFFFULL
                                             : 0x8000000000000000ULL);
}
__device__ __forceinline__ double kinv(unsigned long long k) {
    const long long b = (k & 0x8000000000000000ULL)
                      ? (long long)(k ^ 0x8000000000000000ULL)
                      : ~(long long)k;
    return __longlong_as_double(b);
}

// ---------------------------------------------------------------------------
// Kernel 2: exact JV LSA — R7 structure VERBATIM (v=0 init, f32 row reduction,
// greedy, ARR), with ONLY the warp argmin changed: 3x __reduce_min_sync ladder
// (exact lexicographic 64-bit min, smallest-j tie-break) + bit-exact minv
// reconstruction via the inverse key bijection.
// ---------------------------------------------------------------------------
__global__ __launch_bounds__(128) void lsa_kernel(float* __restrict__ out, int out_size)
{
    const int b    = blockIdx.x;
    const int tid  = threadIdx.x;
    const int lane = tid & 31;
    const int wid  = tid >> 5;
    const float*  __restrict__ ct  = g_ct  + (size_t)b * NT * NQ;
    const double* __restrict__ dct = g_dct + (size_t)b * NT * NQ;

    __shared__ double v[NQ];
    __shared__ double spc[NQ];
    __shared__ double u[NT];
    __shared__ int    path[NQ];
    __shared__ int    row4col[NQ];
    __shared__ int    col4row[NT];
    __shared__ int    jmin[NT];
    __shared__ int    freelist[NT];
    __shared__ unsigned char SC[NQ];
    __shared__ unsigned char SR[NT];
    __shared__ int    s_nf;

    const double DINF = __longlong_as_double(0x7FF0000000000000LL);
    const float  FINF = __int_as_float(0x7F800000);
    const unsigned FULL = 0xffffffffu;

    // ---- global init (all 128 threads) ----
    col4row[tid] = -1;
    for (int j = tid; j < NQ; j += 128) { v[j] = 0.0; row4col[j] = -1; }
    __syncthreads();

    // ---- row reduction: u[i] = min_j c[i][j] (exact in f32) ----
    for (int r = wid; r < NT; r += 4) {
        const float* __restrict__ row = ct + (size_t)r * NQ;
        float m = FINF; int mj = 0;
        for (int j = lane; j < NQ; j += 32) {
            const float c = __ldg(row + j);
            if (c < m) { m = c; mj = j; }
        }
#pragma unroll
        for (int off = 16; off > 0; off >>= 1) {
            const float ov = __shfl_down_sync(FULL, m, off);
            const int   oj = __shfl_down_sync(FULL, mj, off);
            if (ov < m || (ov == m && oj < mj)) { m = ov; mj = oj; }
        }
        if (lane == 0) { u[r] = (double)m; jmin[r] = mj; }
    }
    __syncthreads();

    // ---- greedy zero-assignment + free-row list (thread 0) ----
    if (tid == 0) {
        int nf = 0;
        for (int i = 0; i < NT; i++) {
            const int j = jmin[i];
            if (row4col[j] < 0) { row4col[j] = i; col4row[i] = j; }
            else freelist[nf++] = i;
        }
        s_nf = nf;
    }
    __syncthreads();

    if (wid != 0) return;   // warp 0 carries on alone; no __syncthreads below

    // ======== LAPJV augmenting row reduction (warp-cooperative) ========
    {
        const int nf = s_nf;
        int li = 1;
        int i = (nf > 0) ? freelist[0] : -1;
        int steps = 0;
        const int cap = 4 * nf + 8;
        while (i >= 0 && steps < cap) {
            steps++;
            const double* __restrict__ drow = dct + (size_t)i * NQ;
            double m1 = DINF, m2 = DINF;
            int j1 = -1, j2 = -1;
#pragma unroll
            for (int k = 0; k < NCPL; k++) {
                const int j = (k << 5) + lane;
                if (j < NQ) {
                    const double rc = __ldg(drow + j) - v[j];
                    if (rc < m1)      { m2 = m1; j2 = j1; m1 = rc; j1 = j; }
                    else if (rc < m2) { m2 = rc; j2 = j; }
                }
            }
#pragma unroll
            for (int off = 16; off > 0; off >>= 1) {
                const double om1 = __shfl_down_sync(FULL, m1, off);
                const double om2 = __shfl_down_sync(FULL, m2, off);
                const int    oj1 = __shfl_down_sync(FULL, j1, off);
                const int    oj2 = __shfl_down_sync(FULL, j2, off);
                if (om1 < m1) {
                    if (m1 < om2) { m2 = m1;  j2 = j1;  }
                    else          { m2 = om2; j2 = oj2; }
                    m1 = om1; j1 = oj1;
                } else if (om1 < m2) { m2 = om1; j2 = oj1; }
            }
            int nexti = -1;
            if (lane == 0) {
                const double u1 = m1, u2 = m2;
                int jj = j1;
                u[i] = u2;
                if (u1 < u2)                            v[jj] -= (u2 - u1);
                else if (row4col[jj] >= 0 && j2 >= 0)   jj = j2;   // u1 == u2
                const int kk = row4col[jj];
                row4col[jj] = i; col4row[i] = jj;
                if (kk >= 0) { col4row[kk] = -1; nexti = kk; }
                else         { nexti = (li < nf) ? freelist[li++] : -1; }
            }
            nexti = __shfl_sync(FULL, nexti, 0);
            i = nexti;
            __syncwarp();
        }
    }

    // ======== Dijkstra augmenting phases (single warp) ========
    for (int cur = 0; cur < NT; cur++) {
        if (col4row[cur] >= 0) continue;

        for (int j = lane; j < NQ; j += 32) { spc[j] = DINF; path[j] = -1; SC[j] = 0; }
        for (int r = lane; r < NT; r += 32) SR[r] = 0;
        __syncwarp();

        int i = cur, sink = -1;
        double minv = 0.0;
        while (sink < 0) {
            if (lane == 0) SR[i] = 1;
            const double w = minv - u[i];
            const double* __restrict__ drow = dct + (size_t)i * NQ;

            unsigned long long K0 = ~0ULL, K1 = ~0ULL, K2 = ~0ULL, K3 = ~0ULL;
            int J0 = NQ, J1 = NQ, J2 = NQ, J3 = NQ;
#pragma unroll
            for (int k = 0; k < NCPL; k++) {
                const int j = (k << 5) + lane;
                if (j < NQ && !SC[j]) {
                    double sj = spc[j];
                    const double r = (__ldg(drow + j) + w) - v[j];
                    if (r < sj) { spc[j] = r; path[j] = i; sj = r; }
                    const unsigned long long key = dkey(sj);
                    switch (k & 3) {
                        case 0: if (key < K0) { K0 = key; J0 = j; } break;
                        case 1: if (key < K1) { K1 = key; J1 = j; } break;
                        case 2: if (key < K2) { K2 = key; J2 = j; } break;
                        default:if (key < K3) { K3 = key; J3 = j; } break;
                    }
                }
            }
            // merge 4 accumulators (tie -> smaller j; within each, first-min kept)
            unsigned long long K = K0; int J = J0;
            if (K1 < K || (K1 == K && J1 < J)) { K = K1; J = J1; }
            if (K2 < K || (K2 == K && J2 < J)) { K = K2; J = J2; }
            if (K3 < K || (K3 == K && J3 < J)) { K = K3; J = J3; }

            // exact 64-bit lexicographic argmin via 3x redux (tie -> smaller j)
            const unsigned hi = (unsigned)(K >> 32);
            const unsigned mh = __reduce_min_sync(FULL, hi);
            const unsigned lo = (unsigned)K;
            const unsigned ml = __reduce_min_sync(FULL, (hi == mh) ? lo : 0xffffffffu);
            const bool win = (hi == mh) && (lo == ml);
            const unsigned mj = __reduce_min_sync(FULL, win ? (unsigned)J : 0xffffffffu);
            const int Jw = (int)mj;
            minv = kinv(((unsigned long long)mh << 32) | ml);   // == spc[Jw] bit-exactly

            const int r4c = row4col[Jw];        // phase-stable shared (broadcast)
            if (lane == 0) SC[Jw] = 1;
            if (r4c < 0) sink = Jw; else i = r4c;
            __syncwarp();                 // SC/spc/path stores visible before next sweep
        }

        // dual updates (pre-augmentation state, exact JV formulas)
        for (int r = lane; r < NT; r += 32) {
            if (r == cur)     u[r] += minv;
            else if (SR[r])   u[r] += minv - spc[col4row[r]];
        }
        for (int j = lane; j < NQ; j += 32)
            if (SC[j]) v[j] -= minv - spc[j];
        __syncwarp();

        // augment along the alternating path (lane 0)
        if (lane == 0) {
            int j = sink;
            while (true) {
                const int ii = path[j];
                row4col[j] = ii;
                const int nj = col4row[ii];
                col4row[ii] = j;
                j = nj;
                if (ii == cur) break;
            }
        }
        __syncwarp();
    }

    // ---- emit row_ind / col_ind in sorted-by-query order ----
    if (out_size >= BATCH * NQ * NT + 2 * BATCH * NT) {
        float* rows = out + (size_t)BATCH * NQ * NT;
        float* cols = rows + BATCH * NT;
        for (int t = lane; t < NT; t += 32) {
            const int q = col4row[t];
            int rank = 0;
#pragma unroll 8
            for (int tt = 0; tt < NT; tt++) rank += (col4row[tt] < q) ? 1 : 0;
            rows[b * NT + rank] = (float)q;    // row_ind: sorted query indices
            cols[b * NT + rank] = (float)t;    // col_ind: target for that query
        }
    }
}

// ---------------------------------------------------------------------------
extern "C" void kernel_launch(void* const* d_in, const int* in_sizes, int n_in,
                              void* d_out, int out_size)
{
    const float* pred_boxes = (const float*)d_in[0];   // (16, 500, 4)
    const float* pred_kpts  = (const float*)d_in[1];   // (16, 500, 17, 2)
    const float* tgt_boxes  = (const float*)d_in[2];   // (16, 128, 4)
    const float* tgt_kpts   = (const float*)d_in[3];   // (16, 128, 17, 2)
    float* out = (float*)d_out;

    dim3 grid(NQ, BATCH);
    cost_kernel<<<grid, 128>>>(pred_boxes, pred_kpts, tgt_boxes, tgt_kpts, out);
    lsa_kernel<<<BATCH, 128>>>(out, out_size);
}

// round 11
// speedup vs baseline: 1.1111x; 1.1111x over previous
#include <cuda_runtime.h>
#include <math.h>

// Problem dims (fixed by the reference)
#define BATCH 16
#define NQ    500   // queries (pred) = columns
#define NT    128   // targets       = rows
#define KPT   34    // 17 keypoints * 2
#define NCPL  16    // columns per lane: ceil(500/32)

// Transposed cost scratch: [b][target n][query q]
__device__ float  g_ct [BATCH * NT * NQ];   // f32 (exact row reduction)
__device__ double g_dct[BATCH * NT * NQ];   // f64 (path search)

// ---------------------------------------------------------------------------
// Kernel 1: cost matrix. One block per (b, q), 128 threads = one per target n.
// ---------------------------------------------------------------------------
__global__ __launch_bounds__(128) void cost_kernel(
    const float* __restrict__ pred_boxes,   // (B, Q, 4)  cxcywh
    const float* __restrict__ pred_kpts,    // (B, Q, 17, 2)
    const float* __restrict__ tgt_boxes,    // (B, N, 4)  cxcywh
    const float* __restrict__ tgt_kpts,     // (B, N, 17, 2)
    float* __restrict__ C)                  // (B, Q, N)
{
    const int q = blockIdx.x;
    const int b = blockIdx.y;
    const int n = threadIdx.x;

    __shared__ float s_pk[KPT];
    __shared__ float s_pb[4];
    const float* pbq = pred_boxes + (b * NQ + q) * 4;
    const float* pkq = pred_kpts + (size_t)(b * NQ + q) * KPT;
    if (n < KPT) s_pk[n] = pkq[n];
    if (n < 4)   s_pb[n] = pbq[n];
    __syncthreads();

    const float* tbn = tgt_boxes + (b * NT + n) * 4;
    const float* tkn = tgt_kpts + (size_t)(b * NT + n) * KPT;

    const float p0 = s_pb[0], p1 = s_pb[1], p2 = s_pb[2], p3 = s_pb[3];
    const float t0 = tbn[0], t1 = tbn[1], t2 = tbn[2], t3 = tbn[3];

    float cbbox = fabsf(p0 - t0) + fabsf(p1 - t1) + fabsf(p2 - t2) + fabsf(p3 - t3);

    float px0 = p0 - 0.5f * p2, py0 = p1 - 0.5f * p3;
    float px1 = p0 + 0.5f * p2, py1 = p1 + 0.5f * p3;
    px1 = fmaxf(px1, px0 + 1e-4f);
    py1 = fmaxf(py1, py0 + 1e-4f);
    float tx0 = t0 - 0.5f * t2, ty0 = t1 - 0.5f * t3;
    float tx1 = t0 + 0.5f * t2, ty1 = t1 + 0.5f * t3;
    tx1 = fmaxf(tx1, tx0 + 1e-4f);
    ty1 = fmaxf(ty1, ty0 + 1e-4f);

    const float ap = (px1 - px0) * (py1 - py0);
    const float at = (tx1 - tx0) * (ty1 - ty0);

    const float iw = fmaxf(fminf(px1, tx1) - fmaxf(px0, tx0), 0.0f);
    const float ih = fmaxf(fminf(py1, ty1) - fmaxf(py0, ty0), 0.0f);
    const float inter = iw * ih;
    const float uni = ap + at - inter;
    const float iou = inter / uni;

    const float ew = fmaxf(fmaxf(px1, tx1) - fminf(px0, tx0), 0.0f);
    const float eh = fmaxf(fmaxf(py1, ty1) - fminf(py0, ty0), 0.0f);
    const float enc = ew * eh;
    const float giou = iou - (enc - uni) / enc;

    float ckpt = 0.0f;
#pragma unroll
    for (int k = 0; k < KPT; k++) ckpt += fabsf(s_pk[k] - tkn[k]);

    const float cost = 5.0f * cbbox - 2.0f * giou + 1.0f * ckpt;

    C[(size_t)(b * NQ + q) * NT + n] = cost;
    const size_t ti = (size_t)(b * NT + n) * NQ + q;
    g_ct[ti]  = cost;
    g_dct[ti] = (double)cost;
}

// Monotone bijection double <-> uint64 (order-preserving, exact).
__device__ __forceinline__ unsigned long long dkey(double x) {
    const long long b = __double_as_longlong(x);
    return (unsigned long long)b ^ ((b < 0) ? 0xFFFFFFFFFFFFFFFFULL
                                             : 0x8000000000000000ULL);
}
__device__ __forceinline__ double kinv(unsigned long long k) {
    const long long b = (k & 0x8000000000000000ULL)
                      ? (long long)(k ^ 0x8000000000000000ULL)
                      : ~(long long)k;
    return __longlong_as_double(b);
}

// ---------------------------------------------------------------------------
// Kernel 2: exact JV LSA. Init (verbatim from passing R10): v=0, f32 row
// reduction, greedy, LAPJV ARR. Dijkstra phases: single warp, shortest-path
// keys in per-lane REGISTERS (lane owns columns j == lane mod 32), per-phase
// register cache of v, integer-key compares, 3x redux argmin, compact
// settle-list dual updates. Dual-feasible throughout -> exact unique optimum.
// ---------------------------------------------------------------------------
__global__ __launch_bounds__(128) void lsa_kernel(float* __restrict__ out, int out_size)
{
    const int b    = blockIdx.x;
    const int tid  = threadIdx.x;
    const int lane = tid & 31;
    const int wid  = tid >> 5;
    const float*  __restrict__ ct  = g_ct  + (size_t)b * NT * NQ;
    const double* __restrict__ dct = g_dct + (size_t)b * NT * NQ;

    __shared__ double v[NQ];
    __shared__ double u[NT];
    __shared__ double cdist[NQ];
    __shared__ int    clist[NQ];
    __shared__ int    path[NQ];
    __shared__ int    row4col[NQ];
    __shared__ int    col4row[NT];
    __shared__ int    jmin[NT];
    __shared__ int    freelist[NT];
    __shared__ int    s_nf;

    const double DINF = __longlong_as_double(0x7FF0000000000000LL);
    const float  FINF = __int_as_float(0x7F800000);
    const unsigned FULL = 0xffffffffu;

    // ---- global init (all 128 threads) ----
    col4row[tid] = -1;
    for (int j = tid; j < NQ; j += 128) { v[j] = 0.0; row4col[j] = -1; }
    __syncthreads();

    // ---- row reduction: u[i] = min_j c[i][j] (exact in f32) ----
    for (int r = wid; r < NT; r += 4) {
        const float* __restrict__ row = ct + (size_t)r * NQ;
        float m = FINF; int mj = 0;
        for (int j = lane; j < NQ; j += 32) {
            const float c = __ldg(row + j);
            if (c < m) { m = c; mj = j; }
        }
#pragma unroll
        for (int off = 16; off > 0; off >>= 1) {
            const float ov = __shfl_down_sync(FULL, m, off);
            const int   oj = __shfl_down_sync(FULL, mj, off);
            if (ov < m || (ov == m && oj < mj)) { m = ov; mj = oj; }
        }
        if (lane == 0) { u[r] = (double)m; jmin[r] = mj; }
    }
    __syncthreads();

    // ---- greedy zero-assignment + free-row list (thread 0) ----
    if (tid == 0) {
        int nf = 0;
        for (int i = 0; i < NT; i++) {
            const int j = jmin[i];
            if (row4col[j] < 0) { row4col[j] = i; col4row[i] = j; }
            else freelist[nf++] = i;
        }
        s_nf = nf;
    }
    __syncthreads();

    if (wid != 0) return;   // warp 0 carries on alone; no __syncthreads below

    // ======== LAPJV augmenting row reduction (warp-cooperative) ========
    {
        const int nf = s_nf;
        int li = 1;
        int i = (nf > 0) ? freelist[0] : -1;
        int steps = 0;
        const int cap = 4 * nf + 8;
        while (i >= 0 && steps < cap) {
            steps++;
            const double* __restrict__ drow = dct + (size_t)i * NQ;
            double m1 = DINF, m2 = DINF;
            int j1 = -1, j2 = -1;
#pragma unroll
            for (int k = 0; k < NCPL; k++) {
                const int j = (k << 5) + lane;
                if (j < NQ) {
                    const double rc = __ldg(drow + j) - v[j];
                    if (rc < m1)      { m2 = m1; j2 = j1; m1 = rc; j1 = j; }
                    else if (rc < m2) { m2 = rc; j2 = j; }
                }
            }
#pragma unroll
            for (int off = 16; off > 0; off >>= 1) {
                const double om1 = __shfl_down_sync(FULL, m1, off);
                const double om2 = __shfl_down_sync(FULL, m2, off);
                const int    oj1 = __shfl_down_sync(FULL, j1, off);
                const int    oj2 = __shfl_down_sync(FULL, j2, off);
                if (om1 < m1) {
                    if (m1 < om2) { m2 = m1;  j2 = j1;  }
                    else          { m2 = om2; j2 = oj2; }
                    m1 = om1; j1 = oj1;
                } else if (om1 < m2) { m2 = om1; j2 = oj1; }
            }
            int nexti = -1;
            if (lane == 0) {
                const double u1 = m1, u2 = m2;
                int jj = j1;
                u[i] = u2;
                if (u1 < u2)                            v[jj] -= (u2 - u1);
                else if (row4col[jj] >= 0 && j2 >= 0)   jj = j2;   // u1 == u2
                const int kk = row4col[jj];
                row4col[jj] = i; col4row[i] = jj;
                if (kk >= 0) { col4row[kk] = -1; nexti = kk; }
                else         { nexti = (li < nf) ? freelist[li++] : -1; }
            }
            nexti = __shfl_sync(FULL, nexti, 0);
            i = nexti;
            __syncwarp();
        }
    }

    // ======== Dijkstra augmenting phases (single warp, register state) ======
    for (int cur = 0; cur < NT; cur++) {
        if (col4row[cur] >= 0) continue;

        // per-phase register caches: v values + shortest-path keys + mask
        double vv[NCPL];
        unsigned long long sk[NCPL];
#pragma unroll
        for (int k = 0; k < NCPL; k++) {
            const int j = (k << 5) + lane;
            vv[k] = (j < NQ) ? v[j] : 0.0;
            sk[k] = ~0ULL;
        }
        unsigned ms = (lane < 20) ? 0u : 0x8000u;   // k=15 invalid for lane>=20
        int cnt = 0;
        int i = cur, sink = -1;
        double minv = 0.0;

        while (sink < 0) {
            const double w = minv - u[i];
            const double* __restrict__ drow = dct + (size_t)i * NQ;

            unsigned long long K0 = ~0ULL, K1 = ~0ULL, K2 = ~0ULL, K3 = ~0ULL;
            int J0 = NQ, J1 = NQ, J2 = NQ, J3 = NQ;
#pragma unroll
            for (int k = 0; k < NCPL; k++) {
                const int j = (k << 5) + lane;
                if (!((ms >> k) & 1u)) {
                    const double r = (__ldg(drow + j) + w) - vv[k];
                    const unsigned long long key = dkey(r);
                    if (key < sk[k]) { sk[k] = key; path[j] = i; }
                    const unsigned long long c = sk[k];
                    switch (k & 3) {
                        case 0: if (c < K0) { K0 = c; J0 = j; } break;
                        case 1: if (c < K1) { K1 = c; J1 = j; } break;
                        case 2: if (c < K2) { K2 = c; J2 = j; } break;
                        default:if (c < K3) { K3 = c; J3 = j; } break;
                    }
                }
            }
            // merge 4 accumulators (tie -> smaller j; within each, first-min kept)
            unsigned long long K = K0; int J = J0;
            if (K1 < K || (K1 == K && J1 < J)) { K = K1; J = J1; }
            if (K2 < K || (K2 == K && J2 < J)) { K = K2; J = J2; }
            if (K3 < K || (K3 == K && J3 < J)) { K = K3; J = J3; }

            // exact 64-bit lexicographic argmin via 3x redux (tie -> smaller j)
            const unsigned hi = (unsigned)(K >> 32);
            const unsigned mh = __reduce_min_sync(FULL, hi);
            const unsigned lo = (unsigned)K;
            const unsigned ml = __reduce_min_sync(FULL, (hi == mh) ? lo : 0xffffffffu);
            const bool win = (hi == mh) && (lo == ml);
            const unsigned mj = __reduce_min_sync(FULL, win ? (unsigned)J : 0xffffffffu);
            const int Jw = (int)mj;
            minv = kinv(((unsigned long long)mh << 32) | ml);   // == spc[Jw] bit-exactly

            const int r4c = row4col[Jw];        // phase-stable shared (broadcast)
            if (lane == 0) { clist[cnt] = Jw; cdist[cnt] = minv; }
            cnt++;
            if (lane == (Jw & 31)) ms |= 1u << (Jw >> 5);   // settle: owning lane masks
            if (r4c < 0) sink = Jw; else i = r4c;
        }

        __syncwarp();   // publish clist/cdist/path before cross-lane reads

        // dual updates from the compact settle list (exact JV formulas:
        // settled columns == SC; their assigned rows (+cur) == SR)
        for (int t = lane; t < cnt; t += 32) {
            const int    J = clist[t];
            const double d = cdist[t];
            v[J] -= minv - d;
            const int r = row4col[J];
            if (r >= 0) u[r] += minv - d;
        }
        if (lane == 0) u[cur] += minv;
        __syncwarp();

        // augment along the alternating path (lane 0)
        if (lane == 0) {
            int j = sink;
            while (true) {
                const int ii = path[j];
                row4col[j] = ii;
                const int nj = col4row[ii];
                col4row[ii] = j;
                j = nj;
                if (ii == cur) break;
            }
        }
        __syncwarp();
    }

    // ---- emit row_ind / col_ind in sorted-by-query order ----
    if (out_size >= BATCH * NQ * NT + 2 * BATCH * NT) {
        float* rows = out + (size_t)BATCH * NQ * NT;
        float* cols = rows + BATCH * NT;
        for (int t = lane; t < NT; t += 32) {
            const int q = col4row[t];
            int rank = 0;
#pragma unroll 8
            for (int tt = 0; tt < NT; tt++) rank += (col4row[tt] < q) ? 1 : 0;
            rows[b * NT + rank] = (float)q;    // row_ind: sorted query indices
            cols[b * NT + rank] = (float)t;    // col_ind: target for that query
        }
    }
}

// ---------------------------------------------------------------------------
extern "C" void kernel_launch(void* const* d_in, const int* in_sizes, int n_in,
                              void* d_out, int out_size)
{
    const float* pred_boxes = (const float*)d_in[0];   // (16, 500, 4)
    const float* pred_kpts  = (const float*)d_in[1];   // (16, 500, 17, 2)
    const float* tgt_boxes  = (const float*)d_in[2];   // (16, 128, 4)
    const float* tgt_kpts   = (const float*)d_in[3];   // (16, 128, 17, 2)
    float* out = (float*)d_out;

    dim3 grid(NQ, BATCH);
    cost_kernel<<<grid, 128>>>(pred_boxes, pred_kpts, tgt_boxes, tgt_kpts, out);
    lsa_kernel<<<BATCH, 128>>>(out, out_size);
}

// round 12
// speedup vs baseline: 1.2075x; 1.0867x over previous
#include <cuda_runtime.h>
#include <math.h>

// Problem dims (fixed by the reference)
#define BATCH 16
#define NQ    500   // queries (pred) = columns
#define NT    128   // targets       = rows
#define KPT   34    // 17 keypoints * 2
#define NCPL  16    // columns per lane: ceil(500/32)

// Transposed cost scratch: [b][target n][query q], f32 only.
// (double)f32 widening is exact, so all f64 arithmetic is bit-identical to
// reading a pre-widened f64 matrix — at half the cache footprint.
__device__ float g_ct[BATCH * NT * NQ];

// ---------------------------------------------------------------------------
// Kernel 1: cost matrix. One block per (b, q), 128 threads = one per target n.
// ---------------------------------------------------------------------------
__global__ __launch_bounds__(128) void cost_kernel(
    const float* __restrict__ pred_boxes,   // (B, Q, 4)  cxcywh
    const float* __restrict__ pred_kpts,    // (B, Q, 17, 2)
    const float* __restrict__ tgt_boxes,    // (B, N, 4)  cxcywh
    const float* __restrict__ tgt_kpts,     // (B, N, 17, 2)
    float* __restrict__ C)                  // (B, Q, N)
{
    const int q = blockIdx.x;
    const int b = blockIdx.y;
    const int n = threadIdx.x;

    __shared__ float s_pk[KPT];
    __shared__ float s_pb[4];
    const float* pbq = pred_boxes + (b * NQ + q) * 4;
    const float* pkq = pred_kpts + (size_t)(b * NQ + q) * KPT;
    if (n < KPT) s_pk[n] = pkq[n];
    if (n < 4)   s_pb[n] = pbq[n];
    __syncthreads();

    const float* tbn = tgt_boxes + (b * NT + n) * 4;
    const float* tkn = tgt_kpts + (size_t)(b * NT + n) * KPT;

    const float p0 = s_pb[0], p1 = s_pb[1], p2 = s_pb[2], p3 = s_pb[3];
    const float t0 = tbn[0], t1 = tbn[1], t2 = tbn[2], t3 = tbn[3];

    float cbbox = fabsf(p0 - t0) + fabsf(p1 - t1) + fabsf(p2 - t2) + fabsf(p3 - t3);

    float px0 = p0 - 0.5f * p2, py0 = p1 - 0.5f * p3;
    float px1 = p0 + 0.5f * p2, py1 = p1 + 0.5f * p3;
    px1 = fmaxf(px1, px0 + 1e-4f);
    py1 = fmaxf(py1, py0 + 1e-4f);
    float tx0 = t0 - 0.5f * t2, ty0 = t1 - 0.5f * t3;
    float tx1 = t0 + 0.5f * t2, ty1 = t1 + 0.5f * t3;
    tx1 = fmaxf(tx1, tx0 + 1e-4f);
    ty1 = fmaxf(ty1, ty0 + 1e-4f);

    const float ap = (px1 - px0) * (py1 - py0);
    const float at = (tx1 - tx0) * (ty1 - ty0);

    const float iw = fmaxf(fminf(px1, tx1) - fmaxf(px0, tx0), 0.0f);
    const float ih = fmaxf(fminf(py1, ty1) - fmaxf(py0, ty0), 0.0f);
    const float inter = iw * ih;
    const float uni = ap + at - inter;
    const float iou = inter / uni;

    const float ew = fmaxf(fmaxf(px1, tx1) - fminf(px0, tx0), 0.0f);
    const float eh = fmaxf(fmaxf(py1, ty1) - fminf(py0, ty0), 0.0f);
    const float enc = ew * eh;
    const float giou = iou - (enc - uni) / enc;

    float ckpt = 0.0f;
#pragma unroll
    for (int k = 0; k < KPT; k++) ckpt += fabsf(s_pk[k] - tkn[k]);

    const float cost = 5.0f * cbbox - 2.0f * giou + 1.0f * ckpt;

    C[(size_t)(b * NQ + q) * NT + n] = cost;
    g_ct[(size_t)(b * NT + n) * NQ + q] = cost;   // transposed for LSA rows
}

// Monotone bijection double <-> uint64 (order-preserving, exact).
__device__ __forceinline__ unsigned long long dkey(double x) {
    const long long b = __double_as_longlong(x);
    return (unsigned long long)b ^ ((b < 0) ? 0xFFFFFFFFFFFFFFFFULL
                                             : 0x8000000000000000ULL);
}
__device__ __forceinline__ double kinv(unsigned long long k) {
    const long long b = (k & 0x8000000000000000ULL)
                      ? (long long)(k ^ 0x8000000000000000ULL)
                      : ~(long long)k;
    return __longlong_as_double(b);
}

// ---------------------------------------------------------------------------
// Kernel 2: exact JV LSA (structure identical to passing R11; only the cost
// loads changed from f64 to f32+exact-widen). Init: v=0, f32 row reduction,
// greedy, LAPJV ARR. Dijkstra: single warp, register sk/vv state, redux
// argmin, compact settle-list dual updates.
// ---------------------------------------------------------------------------
__global__ __launch_bounds__(128) void lsa_kernel(float* __restrict__ out, int out_size)
{
    const int b    = blockIdx.x;
    const int tid  = threadIdx.x;
    const int lane = tid & 31;
    const int wid  = tid >> 5;
    const float* __restrict__ ct = g_ct + (size_t)b * NT * NQ;

    __shared__ double v[NQ];
    __shared__ double u[NT];
    __shared__ double cdist[NQ];
    __shared__ int    clist[NQ];
    __shared__ int    path[NQ];
    __shared__ int    row4col[NQ];
    __shared__ int    col4row[NT];
    __shared__ int    jmin[NT];
    __shared__ int    freelist[NT];
    __shared__ int    s_nf;

    const double DINF = __longlong_as_double(0x7FF0000000000000LL);
    const float  FINF = __int_as_float(0x7F800000);
    const unsigned FULL = 0xffffffffu;

    // ---- global init (all 128 threads) ----
    col4row[tid] = -1;
    for (int j = tid; j < NQ; j += 128) { v[j] = 0.0; row4col[j] = -1; }
    __syncthreads();

    // ---- row reduction: u[i] = min_j c[i][j] (exact in f32) ----
    for (int r = wid; r < NT; r += 4) {
        const float* __restrict__ row = ct + (size_t)r * NQ;
        float m = FINF; int mj = 0;
        for (int j = lane; j < NQ; j += 32) {
            const float c = __ldg(row + j);
            if (c < m) { m = c; mj = j; }
        }
#pragma unroll
        for (int off = 16; off > 0; off >>= 1) {
            const float ov = __shfl_down_sync(FULL, m, off);
            const int   oj = __shfl_down_sync(FULL, mj, off);
            if (ov < m || (ov == m && oj < mj)) { m = ov; mj = oj; }
        }
        if (lane == 0) { u[r] = (double)m; jmin[r] = mj; }
    }
    __syncthreads();

    // ---- greedy zero-assignment + free-row list (thread 0) ----
    if (tid == 0) {
        int nf = 0;
        for (int i = 0; i < NT; i++) {
            const int j = jmin[i];
            if (row4col[j] < 0) { row4col[j] = i; col4row[i] = j; }
            else freelist[nf++] = i;
        }
        s_nf = nf;
    }
    __syncthreads();

    if (wid != 0) return;   // warp 0 carries on alone; no __syncthreads below

    // ======== LAPJV augmenting row reduction (warp-cooperative) ========
    {
        const int nf = s_nf;
        int li = 1;
        int i = (nf > 0) ? freelist[0] : -1;
        int steps = 0;
        const int cap = 4 * nf + 8;
        while (i >= 0 && steps < cap) {
            steps++;
            const float* __restrict__ crow = ct + (size_t)i * NQ;
            double m1 = DINF, m2 = DINF;
            int j1 = -1, j2 = -1;
#pragma unroll
            for (int k = 0; k < NCPL; k++) {
                const int j = (k << 5) + lane;
                if (j < NQ) {
                    const double rc = (double)__ldg(crow + j) - v[j];
                    if (rc < m1)      { m2 = m1; j2 = j1; m1 = rc; j1 = j; }
                    else if (rc < m2) { m2 = rc; j2 = j; }
                }
            }
#pragma unroll
            for (int off = 16; off > 0; off >>= 1) {
                const double om1 = __shfl_down_sync(FULL, m1, off);
                const double om2 = __shfl_down_sync(FULL, m2, off);
                const int    oj1 = __shfl_down_sync(FULL, j1, off);
                const int    oj2 = __shfl_down_sync(FULL, j2, off);
                if (om1 < m1) {
                    if (m1 < om2) { m2 = m1;  j2 = j1;  }
                    else          { m2 = om2; j2 = oj2; }
                    m1 = om1; j1 = oj1;
                } else if (om1 < m2) { m2 = om1; j2 = oj1; }
            }
            int nexti = -1;
            if (lane == 0) {
                const double u1 = m1, u2 = m2;
                int jj = j1;
                u[i] = u2;
                if (u1 < u2)                            v[jj] -= (u2 - u1);
                else if (row4col[jj] >= 0 && j2 >= 0)   jj = j2;   // u1 == u2
                const int kk = row4col[jj];
                row4col[jj] = i; col4row[i] = jj;
                if (kk >= 0) { col4row[kk] = -1; nexti = kk; }
                else         { nexti = (li < nf) ? freelist[li++] : -1; }
            }
            nexti = __shfl_sync(FULL, nexti, 0);
            i = nexti;
            __syncwarp();
        }
    }

    // ======== Dijkstra augmenting phases (single warp, register state) ======
    for (int cur = 0; cur < NT; cur++) {
        if (col4row[cur] >= 0) continue;

        // per-phase register caches: v values + shortest-path keys + mask
        double vv[NCPL];
        unsigned long long sk[NCPL];
#pragma unroll
        for (int k = 0; k < NCPL; k++) {
            const int j = (k << 5) + lane;
            vv[k] = (j < NQ) ? v[j] : 0.0;
            sk[k] = ~0ULL;
        }
        unsigned ms = (lane < 20) ? 0u : 0x8000u;   // k=15 invalid for lane>=20
        int cnt = 0;
        int i = cur, sink = -1;
        double minv = 0.0;

        while (sink < 0) {
            const double w = minv - u[i];
            const float* __restrict__ drow = ct + (size_t)i * NQ;

            unsigned long long K0 = ~0ULL, K1 = ~0ULL, K2 = ~0ULL, K3 = ~0ULL;
            int J0 = NQ, J1 = NQ, J2 = NQ, J3 = NQ;
#pragma unroll
            for (int k = 0; k < NCPL; k++) {
                const int j = (k << 5) + lane;
                if (!((ms >> k) & 1u)) {
                    const double r = ((double)__ldg(drow + j) + w) - vv[k];
                    const unsigned long long key = dkey(r);
                    if (key < sk[k]) { sk[k] = key; path[j] = i; }
                    const unsigned long long c = sk[k];
                    switch (k & 3) {
                        case 0: if (c < K0) { K0 = c; J0 = j; } break;
                        case 1: if (c < K1) { K1 = c; J1 = j; } break;
                        case 2: if (c < K2) { K2 = c; J2 = j; } break;
                        default:if (c < K3) { K3 = c; J3 = j; } break;
                    }
                }
            }
            // merge 4 accumulators (tie -> smaller j; within each, first-min kept)
            unsigned long long K = K0; int J = J0;
            if (K1 < K || (K1 == K && J1 < J)) { K = K1; J = J1; }
            if (K2 < K || (K2 == K && J2 < J)) { K = K2; J = J2; }
            if (K3 < K || (K3 == K && J3 < J)) { K = K3; J = J3; }

            // exact 64-bit lexicographic argmin via 3x redux (tie -> smaller j)
            const unsigned hi = (unsigned)(K >> 32);
            const unsigned mh = __reduce_min_sync(FULL, hi);
            const unsigned lo = (unsigned)K;
            const unsigned ml = __reduce_min_sync(FULL, (hi == mh) ? lo : 0xffffffffu);
            const bool win = (hi == mh) && (lo == ml);
            const unsigned mj = __reduce_min_sync(FULL, win ? (unsigned)J : 0xffffffffu);
            const int Jw = (int)mj;
            minv = kinv(((unsigned long long)mh << 32) | ml);   // bit-exact spc[Jw]

            const int r4c = row4col[Jw];        // phase-stable shared (broadcast)
            if (lane == 0) { clist[cnt] = Jw; cdist[cnt] = minv; }
            cnt++;
            if (lane == (Jw & 31)) ms |= 1u << (Jw >> 5);   // settle: owning lane masks
            if (r4c < 0) sink = Jw; else i = r4c;
        }

        __syncwarp();   // publish clist/cdist/path before cross-lane reads

        // dual updates from the compact settle list (exact JV formulas:
        // settled columns == SC; their assigned rows (+cur) == SR)
        for (int t = lane; t < cnt; t += 32) {
            const int    J = clist[t];
            const double d = cdist[t];
            v[J] -= minv - d;
            const int r = row4col[J];
            if (r >= 0) u[r] += minv - d;
        }
        if (lane == 0) u[cur] += minv;
        __syncwarp();

        // augment along the alternating path (lane 0)
        if (lane == 0) {
            int j = sink;
            while (true) {
                const int ii = path[j];
                row4col[j] = ii;
                const int nj = col4row[ii];
                col4row[ii] = j;
                j = nj;
                if (ii == cur) break;
            }
        }
        __syncwarp();
    }

    // ---- emit row_ind / col_ind in sorted-by-query order ----
    if (out_size >= BATCH * NQ * NT + 2 * BATCH * NT) {
        float* rows = out + (size_t)BATCH * NQ * NT;
        float* cols = rows + BATCH * NT;
        for (int t = lane; t < NT; t += 32) {
            const int q = col4row[t];
            int rank = 0;
#pragma unroll 8
            for (int tt = 0; tt < NT; tt++) rank += (col4row[tt] < q) ? 1 : 0;
            rows[b * NT + rank] = (float)q;    // row_ind: sorted query indices
            cols[b * NT + rank] = (float)t;    // col_ind: target for that query
        }
    }
}

// ---------------------------------------------------------------------------
extern "C" void kernel_launch(void* const* d_in, const int* in_sizes, int n_in,
                              void* d_out, int out_size)
{
    const float* pred_boxes = (const float*)d_in[0];   // (16, 500, 4)
    const float* pred_kpts  = (const float*)d_in[1];   // (16, 500, 17, 2)
    const float* tgt_boxes  = (const float*)d_in[2];   // (16, 128, 4)
    const float* tgt_kpts   = (const float*)d_in[3];   // (16, 128, 17, 2)
    float* out = (float*)d_out;

    dim3 grid(NQ, BATCH);
    cost_kernel<<<grid, 128>>>(pred_boxes, pred_kpts, tgt_boxes, tgt_kpts, out);
    lsa_kernel<<<BATCH, 128>>>(out, out_size);
}

// round 13
// speedup vs baseline: 1.2276x; 1.0167x over previous
#include <cuda_runtime.h>
#include <math.h>

// Problem dims (fixed by the reference)
#define BATCH 16
#define NQ    500   // queries (pred) = columns
#define NT    128   // targets       = rows
#define KPT   34    // 17 keypoints * 2
#define NCPL  16    // columns per lane: ceil(500/32)

// Transposed cost scratch: [b][target n][query q], f32 only.
// (double)f32 widening is exact -> f64 arithmetic bit-identical to a
// pre-widened f64 matrix at half the cache footprint.
__device__ float g_ct[BATCH * NT * NQ];

// ---------------------------------------------------------------------------
// Kernel 1: cost matrix. One block per (b, q), 128 threads = one per target n.
// Writes only C (coalesced); the transpose is a separate tiled kernel.
// ---------------------------------------------------------------------------
__global__ __launch_bounds__(128) void cost_kernel(
    const float* __restrict__ pred_boxes,   // (B, Q, 4)  cxcywh
    const float* __restrict__ pred_kpts,    // (B, Q, 17, 2)
    const float* __restrict__ tgt_boxes,    // (B, N, 4)  cxcywh
    const float* __restrict__ tgt_kpts,     // (B, N, 17, 2)
    float* __restrict__ C)                  // (B, Q, N)
{
    const int q = blockIdx.x;
    const int b = blockIdx.y;
    const int n = threadIdx.x;

    __shared__ float s_pk[KPT];
    __shared__ float s_pb[4];
    const float* pbq = pred_boxes + (b * NQ + q) * 4;
    const float* pkq = pred_kpts + (size_t)(b * NQ + q) * KPT;
    if (n < KPT) s_pk[n] = pkq[n];
    if (n < 4)   s_pb[n] = pbq[n];
    __syncthreads();

    const float* tbn = tgt_boxes + (b * NT + n) * 4;
    const float* tkn = tgt_kpts + (size_t)(b * NT + n) * KPT;

    const float p0 = s_pb[0], p1 = s_pb[1], p2 = s_pb[2], p3 = s_pb[3];
    const float t0 = tbn[0], t1 = tbn[1], t2 = tbn[2], t3 = tbn[3];

    float cbbox = fabsf(p0 - t0) + fabsf(p1 - t1) + fabsf(p2 - t2) + fabsf(p3 - t3);

    float px0 = p0 - 0.5f * p2, py0 = p1 - 0.5f * p3;
    float px1 = p0 + 0.5f * p2, py1 = p1 + 0.5f * p3;
    px1 = fmaxf(px1, px0 + 1e-4f);
    py1 = fmaxf(py1, py0 + 1e-4f);
    float tx0 = t0 - 0.5f * t2, ty0 = t1 - 0.5f * t3;
    float tx1 = t0 + 0.5f * t2, ty1 = t1 + 0.5f * t3;
    tx1 = fmaxf(tx1, tx0 + 1e-4f);
    ty1 = fmaxf(ty1, ty0 + 1e-4f);

    const float ap = (px1 - px0) * (py1 - py0);
    const float at = (tx1 - tx0) * (ty1 - ty0);

    const float iw = fmaxf(fminf(px1, tx1) - fmaxf(px0, tx0), 0.0f);
    const float ih = fmaxf(fminf(py1, ty1) - fmaxf(py0, ty0), 0.0f);
    const float inter = iw * ih;
    const float uni = ap + at - inter;
    const float iou = inter / uni;

    const float ew = fmaxf(fmaxf(px1, tx1) - fminf(px0, tx0), 0.0f);
    const float eh = fmaxf(fmaxf(py1, ty1) - fminf(py0, ty0), 0.0f);
    const float enc = ew * eh;
    const float giou = iou - (enc - uni) / enc;

    float ckpt = 0.0f;
#pragma unroll
    for (int k = 0; k < KPT; k++) ckpt += fabsf(s_pk[k] - tkn[k]);

    C[(size_t)(b * NQ + q) * NT + n] = 5.0f * cbbox - 2.0f * giou + 1.0f * ckpt;
}

// ---------------------------------------------------------------------------
// Kernel 1b: tiled transpose C (B,Q,N) -> g_ct (B,N,Q). Coalesced both ways.
// ---------------------------------------------------------------------------
__global__ __launch_bounds__(256) void transpose_kernel(const float* __restrict__ C)
{
    __shared__ float tile[32][33];
    const int b  = blockIdx.z;
    const int q0 = blockIdx.x * 32;   // 16 blocks cover 500 (guarded)
    const int n0 = blockIdx.y * 32;   // 4 blocks cover 128
    const int tx = threadIdx.x;       // 0..31
    const int ty = threadIdx.y;       // 0..7

#pragma unroll
    for (int s = 0; s < 32; s += 8) {
        const int q = q0 + ty + s;
        if (q < NQ) tile[ty + s][tx] = C[((size_t)b * NQ + q) * NT + n0 + tx];
    }
    __syncthreads();
#pragma unroll
    for (int s = 0; s < 32; s += 8) {
        const int n = n0 + ty + s;
        const int q = q0 + tx;
        if (q < NQ) g_ct[((size_t)b * NT + n) * NQ + q] = tile[tx][ty + s];
    }
}

// Monotone bijection double <-> uint64 (order-preserving, exact).
__device__ __forceinline__ unsigned long long dkey(double x) {
    const long long b = __double_as_longlong(x);
    return (unsigned long long)b ^ ((b < 0) ? 0xFFFFFFFFFFFFFFFFULL
                                             : 0x8000000000000000ULL);
}
__device__ __forceinline__ double kinv(unsigned long long k) {
    const long long b = (k & 0x8000000000000000ULL)
                      ? (long long)(k ^ 0x8000000000000000ULL)
                      : ~(long long)k;
    return __longlong_as_double(b);
}

// ---------------------------------------------------------------------------
// Kernel 2: exact JV LSA (passing R12 structure). New this round:
//  - per-phase packed snapshot pk[j] = {u[row4col[j]], row4col[j]} -> one
//    LDS.128 on the scalar chain instead of two dependent LDS
//  - ballot fast-path in the argmin (falls back to the exact redux ladder;
//    identical tie-break semantics)
// ---------------------------------------------------------------------------
__global__ __launch_bounds__(128) void lsa_kernel(float* __restrict__ out, int out_size)
{
    const int b    = blockIdx.x;
    const int tid  = threadIdx.x;
    const int lane = tid & 31;
    const int wid  = tid >> 5;
    const float* __restrict__ ct = g_ct + (size_t)b * NT * NQ;

    __shared__ double v[NQ];
    __shared__ double u[NT];
    __shared__ double cdist[NQ];
    __shared__ ulonglong2 pk[NQ];       // per-phase: {u[row4col[j]] bits, row4col[j]}
    __shared__ int    clist[NQ];
    __shared__ int    path[NQ];
    __shared__ int    row4col[NQ];
    __shared__ int    col4row[NT];
    __shared__ int    jmin[NT];
    __shared__ int    freelist[NT];
    __shared__ int    s_nf;

    const double DINF = __longlong_as_double(0x7FF0000000000000LL);
    const float  FINF = __int_as_float(0x7F800000);
    const unsigned FULL = 0xffffffffu;

    // ---- global init (all 128 threads) ----
    col4row[tid] = -1;
    for (int j = tid; j < NQ; j += 128) { v[j] = 0.0; row4col[j] = -1; }
    __syncthreads();

    // ---- row reduction: u[i] = min_j c[i][j] (exact in f32) ----
    for (int r = wid; r < NT; r += 4) {
        const float* __restrict__ row = ct + (size_t)r * NQ;
        float m = FINF; int mj = 0;
        for (int j = lane; j < NQ; j += 32) {
            const float c = __ldg(row + j);
            if (c < m) { m = c; mj = j; }
        }
#pragma unroll
        for (int off = 16; off > 0; off >>= 1) {
            const float ov = __shfl_down_sync(FULL, m, off);
            const int   oj = __shfl_down_sync(FULL, mj, off);
            if (ov < m || (ov == m && oj < mj)) { m = ov; mj = oj; }
        }
        if (lane == 0) { u[r] = (double)m; jmin[r] = mj; }
    }
    __syncthreads();

    // ---- greedy zero-assignment + free-row list (thread 0) ----
    if (tid == 0) {
        int nf = 0;
        for (int i = 0; i < NT; i++) {
            const int j = jmin[i];
            if (row4col[j] < 0) { row4col[j] = i; col4row[i] = j; }
            else freelist[nf++] = i;
        }
        s_nf = nf;
    }
    __syncthreads();

    if (wid != 0) return;   // warp 0 carries on alone; no __syncthreads below

    // ======== LAPJV augmenting row reduction (warp-cooperative) ========
    {
        const int nf = s_nf;
        int li = 1;
        int i = (nf > 0) ? freelist[0] : -1;
        int steps = 0;
        const int cap = 4 * nf + 8;
        while (i >= 0 && steps < cap) {
            steps++;
            const float* __restrict__ crow = ct + (size_t)i * NQ;
            double m1 = DINF, m2 = DINF;
            int j1 = -1, j2 = -1;
#pragma unroll
            for (int k = 0; k < NCPL; k++) {
                const int j = (k << 5) + lane;
                if (j < NQ) {
                    const double rc = (double)__ldg(crow + j) - v[j];
                    if (rc < m1)      { m2 = m1; j2 = j1; m1 = rc; j1 = j; }
                    else if (rc < m2) { m2 = rc; j2 = j; }
                }
            }
#pragma unroll
            for (int off = 16; off > 0; off >>= 1) {
                const double om1 = __shfl_down_sync(FULL, m1, off);
                const double om2 = __shfl_down_sync(FULL, m2, off);
                const int    oj1 = __shfl_down_sync(FULL, j1, off);
                const int    oj2 = __shfl_down_sync(FULL, j2, off);
                if (om1 < m1) {
                    if (m1 < om2) { m2 = m1;  j2 = j1;  }
                    else          { m2 = om2; j2 = oj2; }
                    m1 = om1; j1 = oj1;
                } else if (om1 < m2) { m2 = om1; j2 = oj1; }
            }
            int nexti = -1;
            if (lane == 0) {
                const double u1 = m1, u2 = m2;
                int jj = j1;
                u[i] = u2;
                if (u1 < u2)                            v[jj] -= (u2 - u1);
                else if (row4col[jj] >= 0 && j2 >= 0)   jj = j2;   // u1 == u2
                const int kk = row4col[jj];
                row4col[jj] = i; col4row[i] = jj;
                if (kk >= 0) { col4row[kk] = -1; nexti = kk; }
                else         { nexti = (li < nf) ? freelist[li++] : -1; }
            }
            nexti = __shfl_sync(FULL, nexti, 0);
            i = nexti;
            __syncwarp();
        }
    }

    // ======== Dijkstra augmenting phases (single warp, register state) ======
    for (int cur = 0; cur < NT; cur++) {
        if (col4row[cur] >= 0) continue;

        // per-phase packed snapshot (row4col and u are phase-stable)
        for (int j = lane; j < NQ; j += 32) {
            const int r = row4col[j];
            pk[j] = make_ulonglong2(
                (unsigned long long)__double_as_longlong(r >= 0 ? u[r] : 0.0),
                (unsigned long long)(long long)r);
        }
        // per-phase register caches: v values + shortest-path keys + mask
        double vv[NCPL];
        unsigned long long sk[NCPL];
#pragma unroll
        for (int k = 0; k < NCPL; k++) {
            const int j = (k << 5) + lane;
            vv[k] = (j < NQ) ? v[j] : 0.0;
            sk[k] = ~0ULL;
        }
        unsigned ms = (lane < 20) ? 0u : 0x8000u;   // k=15 invalid for lane>=20
        int cnt = 0;
        int sink = -1;
        double minv = 0.0;
        double w = -u[cur];          // first expansion: i = cur
        int i = cur;
        __syncwarp();                // pk visible

        while (sink < 0) {
            const float* __restrict__ drow = ct + (size_t)i * NQ;

            unsigned long long K0 = ~0ULL, K1 = ~0ULL, K2 = ~0ULL, K3 = ~0ULL;
            int J0 = NQ, J1 = NQ, J2 = NQ, J3 = NQ;
#pragma unroll
            for (int k = 0; k < NCPL; k++) {
                const int j = (k << 5) + lane;
                if (!((ms >> k) & 1u)) {
                    const double r = ((double)__ldg(drow + j) + w) - vv[k];
                    const unsigned long long key = dkey(r);
                    if (key < sk[k]) { sk[k] = key; path[j] = i; }
                    const unsigned long long c = sk[k];
                    switch (k & 3) {
                        case 0: if (c < K0) { K0 = c; J0 = j; } break;
                        case 1: if (c < K1) { K1 = c; J1 = j; } break;
                        case 2: if (c < K2) { K2 = c; J2 = j; } break;
                        default:if (c < K3) { K3 = c; J3 = j; } break;
                    }
                }
            }
            // merge 4 accumulators (tie -> smaller j; within each, first-min kept)
            unsigned long long K = K0; int J = J0;
            if (K1 < K || (K1 == K && J1 < J)) { K = K1; J = J1; }
            if (K2 < K || (K2 == K && J2 < J)) { K = K2; J = J2; }
            if (K3 < K || (K3 == K && J3 < J)) { K = K3; J = J3; }

            // exact 64-bit lexicographic argmin (tie -> smaller j):
            // redux on hi32, then ballot fast-path when the winner is unique.
            const unsigned hi = (unsigned)(K >> 32);
            const unsigned lo = (unsigned)K;
            const unsigned mh = __reduce_min_sync(FULL, hi);
            const unsigned bal1 = __ballot_sync(FULL, hi == mh);
            int Jw; unsigned mlv;
            if (__popc(bal1) == 1) {
                const int src = __ffs(bal1) - 1;
                Jw  = __shfl_sync(FULL, J, src);
                mlv = __shfl_sync(FULL, lo, src);
            } else {
                const unsigned ml = __reduce_min_sync(FULL, (hi == mh) ? lo : 0xffffffffu);
                const bool win = (hi == mh) && (lo == ml);
                const unsigned bal2 = __ballot_sync(FULL, win);
                if (__popc(bal2) == 1) {
                    Jw = __shfl_sync(FULL, J, __ffs(bal2) - 1);
                } else {
                    Jw = (int)__reduce_min_sync(FULL, win ? (unsigned)J : 0xffffffffu);
                }
                mlv = ml;
            }
            minv = kinv(((unsigned long long)mh << 32) | mlv);   // bit-exact spc[Jw]

            // one LDS.128: {u[row4col[Jw]], row4col[Jw]} (phase-stable snapshot)
            const ulonglong2 p = pk[Jw];
            const int r4c = (int)(long long)p.y;
            if (lane == 0) { clist[cnt] = Jw; cdist[cnt] = minv; }
            cnt++;
            if (lane == (Jw & 31)) ms |= 1u << (Jw >> 5);   // settle: owning lane masks
            if (r4c < 0) { sink = Jw; }
            else { i = r4c; w = minv - __longlong_as_double((long long)p.x); }
        }

        __syncwarp();   // publish clist/cdist/path before cross-lane reads

        // dual updates from the compact settle list (exact JV formulas)
        for (int t = lane; t < cnt; t += 32) {
            const int    J = clist[t];
            const double d = cdist[t];
            v[J] -= minv - d;
            const int r = (int)(long long)pk[J].y;
            if (r >= 0) u[r] += minv - d;
        }
        if (lane == 0) u[cur] += minv;
        __syncwarp();

        // augment along the alternating path (lane 0)
        if (lane == 0) {
            int j = sink;
            while (true) {
                const int ii = path[j];
                row4col[j] = ii;
                const int nj = col4row[ii];
                col4row[ii] = j;
                j = nj;
                if (ii == cur) break;
            }
        }
        __syncwarp();
    }

    // ---- emit row_ind / col_ind in sorted-by-query order ----
    if (out_size >= BATCH * NQ * NT + 2 * BATCH * NT) {
        float* rows = out + (size_t)BATCH * NQ * NT;
        float* cols = rows + BATCH * NT;
        for (int t = lane; t < NT; t += 32) {
            const int q = col4row[t];
            int rank = 0;
#pragma unroll 8
            for (int tt = 0; tt < NT; tt++) rank += (col4row[tt] < q) ? 1 : 0;
            rows[b * NT + rank] = (float)q;    // row_ind: sorted query indices
            cols[b * NT + rank] = (float)t;    // col_ind: target for that query
        }
    }
}

// ---------------------------------------------------------------------------
extern "C" void kernel_launch(void* const* d_in, const int* in_sizes, int n_in,
                              void* d_out, int out_size)
{
    const float* pred_boxes = (const float*)d_in[0];   // (16, 500, 4)
    const float* pred_kpts  = (const float*)d_in[1];   // (16, 500, 17, 2)
    const float* tgt_boxes  = (const float*)d_in[2];   // (16, 128, 4)
    const float* tgt_kpts   = (const float*)d_in[3];   // (16, 128, 17, 2)
    float* out = (float*)d_out;

    dim3 cgrid(NQ, BATCH);
    cost_kernel<<<cgrid, 128>>>(pred_boxes, pred_kpts, tgt_boxes, tgt_kpts, out);
    dim3 tgrid(16, NT / 32, BATCH);
    transpose_kernel<<<tgrid, dim3(32, 8)>>>(out);
    lsa_kernel<<<BATCH, 128>>>(out, out_size);
}

// round 14
// speedup vs baseline: 1.4615x; 1.1906x over previous
#include <cuda_runtime.h>
#include <math.h>

// Problem dims (fixed by the reference)
#define BATCH 16
#define NQ    500   // queries (pred) = columns
#define NT    128   // targets       = rows
#define KPT   34    // 17 keypoints * 2
#define NCPL  16    // columns per lane: ceil(500/32)
#define QT    4     // queries per cost block (500 = 125 * 4)

// Transposed cost scratch: [b][target n][query q], f32 only.
// (double)f32 widening is exact -> f64 arithmetic bit-identical to a
// pre-widened f64 matrix at half the cache footprint.
__device__ float g_ct[BATCH * NT * NQ];

// ---------------------------------------------------------------------------
// Kernel 1: cost matrix. One block per (b, 4 queries), 128 threads = one per
// target n. Target box+keypoints live in REGISTERS and are reused across the
// 4 queries (4x less L1 traffic). Writes C coalesced and g_ct as one aligned
// float4 per thread (fused transpose).
// ---------------------------------------------------------------------------
__global__ __launch_bounds__(128) void cost_kernel(
    const float* __restrict__ pred_boxes,   // (B, Q, 4)  cxcywh
    const float* __restrict__ pred_kpts,    // (B, Q, 17, 2)
    const float* __restrict__ tgt_boxes,    // (B, N, 4)  cxcywh
    const float* __restrict__ tgt_kpts,     // (B, N, 17, 2)
    float* __restrict__ C)                  // (B, Q, N)
{
    const int q0 = blockIdx.x * QT;
    const int b  = blockIdx.y;
    const int n  = threadIdx.x;

    __shared__ float s_pk[QT][KPT];
    __shared__ float s_pb[QT][4];
    // cooperative load of the 4 queries' pred data (QT*(KPT+4) = 152 floats)
    for (int x = n; x < QT * KPT; x += 128)
        s_pk[x / KPT][x % KPT] = pred_kpts[(size_t)(b * NQ + q0 + x / KPT) * KPT + (x % KPT)];
    if (n < QT * 4)
        s_pb[n >> 2][n & 3] = pred_boxes[(b * NQ + q0 + (n >> 2)) * 4 + (n & 3)];
    __syncthreads();

    // target data -> registers (reused for all QT queries)
    const float* tbn = tgt_boxes + (b * NT + n) * 4;
    const float t0 = __ldg(tbn + 0), t1 = __ldg(tbn + 1);
    const float t2 = __ldg(tbn + 2), t3 = __ldg(tbn + 3);
    float tx0 = t0 - 0.5f * t2, ty0 = t1 - 0.5f * t3;
    float tx1 = t0 + 0.5f * t2, ty1 = t1 + 0.5f * t3;
    tx1 = fmaxf(tx1, tx0 + 1e-4f);
    ty1 = fmaxf(ty1, ty0 + 1e-4f);
    const float at = (tx1 - tx0) * (ty1 - ty0);

    float tk[KPT];
    {
        const float2* tk2 = (const float2*)(tgt_kpts + (size_t)(b * NT + n) * KPT);
#pragma unroll
        for (int k = 0; k < KPT / 2; k++) {
            const float2 p = __ldg(tk2 + k);
            tk[2 * k] = p.x; tk[2 * k + 1] = p.y;
        }
    }

    float res[QT];
#pragma unroll
    for (int t = 0; t < QT; t++) {
        const float p0 = s_pb[t][0], p1 = s_pb[t][1], p2 = s_pb[t][2], p3 = s_pb[t][3];

        float cbbox = fabsf(p0 - t0) + fabsf(p1 - t1) + fabsf(p2 - t2) + fabsf(p3 - t3);

        float px0 = p0 - 0.5f * p2, py0 = p1 - 0.5f * p3;
        float px1 = p0 + 0.5f * p2, py1 = p1 + 0.5f * p3;
        px1 = fmaxf(px1, px0 + 1e-4f);
        py1 = fmaxf(py1, py0 + 1e-4f);

        const float ap = (px1 - px0) * (py1 - py0);

        const float iw = fmaxf(fminf(px1, tx1) - fmaxf(px0, tx0), 0.0f);
        const float ih = fmaxf(fminf(py1, ty1) - fmaxf(py0, ty0), 0.0f);
        const float inter = iw * ih;
        const float uni = ap + at - inter;
        const float iou = inter / uni;

        const float ew = fmaxf(fmaxf(px1, tx1) - fminf(px0, tx0), 0.0f);
        const float eh = fmaxf(fmaxf(py1, ty1) - fminf(py0, ty0), 0.0f);
        const float enc = ew * eh;
        const float giou = iou - (enc - uni) / enc;

        float ckpt = 0.0f;
#pragma unroll
        for (int k = 0; k < KPT; k++) ckpt += fabsf(s_pk[t][k] - tk[k]);

        const float cost = 5.0f * cbbox - 2.0f * giou + 1.0f * ckpt;
        res[t] = cost;
        C[(size_t)(b * NQ + q0 + t) * NT + n] = cost;   // coalesced across n
    }
    // fused transpose store: row n, columns q0..q0+3 (16B-aligned float4)
    *(float4*)(g_ct + (size_t)(b * NT + n) * NQ + q0) =
        make_float4(res[0], res[1], res[2], res[3]);
}

// Monotone bijection double <-> uint64 (order-preserving, exact).
__device__ __forceinline__ unsigned long long dkey(double x) {
    const long long b = __double_as_longlong(x);
    return (unsigned long long)b ^ ((b < 0) ? 0xFFFFFFFFFFFFFFFFULL
                                             : 0x8000000000000000ULL);
}
__device__ __forceinline__ double kinv(unsigned long long k) {
    const long long b = (k & 0x8000000000000000ULL)
                      ? (long long)(k ^ 0x8000000000000000ULL)
                      : ~(long long)k;
    return __longlong_as_double(b);
}

// ---------------------------------------------------------------------------
// Kernel 2: exact JV LSA — byte-identical to passing R13.
// ---------------------------------------------------------------------------
__global__ __launch_bounds__(128) void lsa_kernel(float* __restrict__ out, int out_size)
{
    const int b    = blockIdx.x;
    const int tid  = threadIdx.x;
    const int lane = tid & 31;
    const int wid  = tid >> 5;
    const float* __restrict__ ct = g_ct + (size_t)b * NT * NQ;

    __shared__ double v[NQ];
    __shared__ double u[NT];
    __shared__ double cdist[NQ];
    __shared__ ulonglong2 pk[NQ];       // per-phase: {u[row4col[j]] bits, row4col[j]}
    __shared__ int    clist[NQ];
    __shared__ int    path[NQ];
    __shared__ int    row4col[NQ];
    __shared__ int    col4row[NT];
    __shared__ int    jmin[NT];
    __shared__ int    freelist[NT];
    __shared__ int    s_nf;

    const double DINF = __longlong_as_double(0x7FF0000000000000LL);
    const float  FINF = __int_as_float(0x7F800000);
    const unsigned FULL = 0xffffffffu;

    // ---- global init (all 128 threads) ----
    col4row[tid] = -1;
    for (int j = tid; j < NQ; j += 128) { v[j] = 0.0; row4col[j] = -1; }
    __syncthreads();

    // ---- row reduction: u[i] = min_j c[i][j] (exact in f32) ----
    for (int r = wid; r < NT; r += 4) {
        const float* __restrict__ row = ct + (size_t)r * NQ;
        float m = FINF; int mj = 0;
        for (int j = lane; j < NQ; j += 32) {
            const float c = __ldg(row + j);
            if (c < m) { m = c; mj = j; }
        }
#pragma unroll
        for (int off = 16; off > 0; off >>= 1) {
            const float ov = __shfl_down_sync(FULL, m, off);
            const int   oj = __shfl_down_sync(FULL, mj, off);
            if (ov < m || (ov == m && oj < mj)) { m = ov; mj = oj; }
        }
        if (lane == 0) { u[r] = (double)m; jmin[r] = mj; }
    }
    __syncthreads();

    // ---- greedy zero-assignment + free-row list (thread 0) ----
    if (tid == 0) {
        int nf = 0;
        for (int i = 0; i < NT; i++) {
            const int j = jmin[i];
            if (row4col[j] < 0) { row4col[j] = i; col4row[i] = j; }
            else freelist[nf++] = i;
        }
        s_nf = nf;
    }
    __syncthreads();

    if (wid != 0) return;   // warp 0 carries on alone; no __syncthreads below

    // ======== LAPJV augmenting row reduction (warp-cooperative) ========
    {
        const int nf = s_nf;
        int li = 1;
        int i = (nf > 0) ? freelist[0] : -1;
        int steps = 0;
        const int cap = 4 * nf + 8;
        while (i >= 0 && steps < cap) {
            steps++;
            const float* __restrict__ crow = ct + (size_t)i * NQ;
            double m1 = DINF, m2 = DINF;
            int j1 = -1, j2 = -1;
#pragma unroll
            for (int k = 0; k < NCPL; k++) {
                const int j = (k << 5) + lane;
                if (j < NQ) {
                    const double rc = (double)__ldg(crow + j) - v[j];
                    if (rc < m1)      { m2 = m1; j2 = j1; m1 = rc; j1 = j; }
                    else if (rc < m2) { m2 = rc; j2 = j; }
                }
            }
#pragma unroll
            for (int off = 16; off > 0; off >>= 1) {
                const double om1 = __shfl_down_sync(FULL, m1, off);
                const double om2 = __shfl_down_sync(FULL, m2, off);
                const int    oj1 = __shfl_down_sync(FULL, j1, off);
                const int    oj2 = __shfl_down_sync(FULL, j2, off);
                if (om1 < m1) {
                    if (m1 < om2) { m2 = m1;  j2 = j1;  }
                    else          { m2 = om2; j2 = oj2; }
                    m1 = om1; j1 = oj1;
                } else if (om1 < m2) { m2 = om1; j2 = oj1; }
            }
            int nexti = -1;
            if (lane == 0) {
                const double u1 = m1, u2 = m2;
                int jj = j1;
                u[i] = u2;
                if (u1 < u2)                            v[jj] -= (u2 - u1);
                else if (row4col[jj] >= 0 && j2 >= 0)   jj = j2;   // u1 == u2
                const int kk = row4col[jj];
                row4col[jj] = i; col4row[i] = jj;
                if (kk >= 0) { col4row[kk] = -1; nexti = kk; }
                else         { nexti = (li < nf) ? freelist[li++] : -1; }
            }
            nexti = __shfl_sync(FULL, nexti, 0);
            i = nexti;
            __syncwarp();
        }
    }

    // ======== Dijkstra augmenting phases (single warp, register state) ======
    for (int cur = 0; cur < NT; cur++) {
        if (col4row[cur] >= 0) continue;

        // per-phase packed snapshot (row4col and u are phase-stable)
        for (int j = lane; j < NQ; j += 32) {
            const int r = row4col[j];
            pk[j] = make_ulonglong2(
                (unsigned long long)__double_as_longlong(r >= 0 ? u[r] : 0.0),
                (unsigned long long)(long long)r);
        }
        // per-phase register caches: v values + shortest-path keys + mask
        double vv[NCPL];
        unsigned long long sk[NCPL];
#pragma unroll
        for (int k = 0; k < NCPL; k++) {
            const int j = (k << 5) + lane;
            vv[k] = (j < NQ) ? v[j] : 0.0;
            sk[k] = ~0ULL;
        }
        unsigned ms = (lane < 20) ? 0u : 0x8000u;   // k=15 invalid for lane>=20
        int cnt = 0;
        int sink = -1;
        double minv = 0.0;
        double w = -u[cur];          // first expansion: i = cur
        int i = cur;
        __syncwarp();                // pk visible

        while (sink < 0) {
            const float* __restrict__ drow = ct + (size_t)i * NQ;

            unsigned long long K0 = ~0ULL, K1 = ~0ULL, K2 = ~0ULL, K3 = ~0ULL;
            int J0 = NQ, J1 = NQ, J2 = NQ, J3 = NQ;
#pragma unroll
            for (int k = 0; k < NCPL; k++) {
                const int j = (k << 5) + lane;
                if (!((ms >> k) & 1u)) {
                    const double r = ((double)__ldg(drow + j) + w) - vv[k];
                    const unsigned long long key = dkey(r);
                    if (key < sk[k]) { sk[k] = key; path[j] = i; }
                    const unsigned long long c = sk[k];
                    switch (k & 3) {
                        case 0: if (c < K0) { K0 = c; J0 = j; } break;
                        case 1: if (c < K1) { K1 = c; J1 = j; } break;
                        case 2: if (c < K2) { K2 = c; J2 = j; } break;
                        default:if (c < K3) { K3 = c; J3 = j; } break;
                    }
                }
            }
            // merge 4 accumulators (tie -> smaller j; within each, first-min kept)
            unsigned long long K = K0; int J = J0;
            if (K1 < K || (K1 == K && J1 < J)) { K = K1; J = J1; }
            if (K2 < K || (K2 == K && J2 < J)) { K = K2; J = J2; }
            if (K3 < K || (K3 == K && J3 < J)) { K = K3; J = J3; }

            // exact 64-bit lexicographic argmin (tie -> smaller j):
            // redux on hi32, then ballot fast-path when the winner is unique.
            const unsigned hi = (unsigned)(K >> 32);
            const unsigned lo = (unsigned)K;
            const unsigned mh = __reduce_min_sync(FULL, hi);
            const unsigned bal1 = __ballot_sync(FULL, hi == mh);
            int Jw; unsigned mlv;
            if (__popc(bal1) == 1) {
                const int src = __ffs(bal1) - 1;
                Jw  = __shfl_sync(FULL, J, src);
                mlv = __shfl_sync(FULL, lo, src);
            } else {
                const unsigned ml = __reduce_min_sync(FULL, (hi == mh) ? lo : 0xffffffffu);
                const bool win = (hi == mh) && (lo == ml);
                const unsigned bal2 = __ballot_sync(FULL, win);
                if (__popc(bal2) == 1) {
                    Jw = __shfl_sync(FULL, J, __ffs(bal2) - 1);
                } else {
                    Jw = (int)__reduce_min_sync(FULL, win ? (unsigned)J : 0xffffffffu);
                }
                mlv = ml;
            }
            minv = kinv(((unsigned long long)mh << 32) | mlv);   // bit-exact spc[Jw]

            // one LDS.128: {u[row4col[Jw]], row4col[Jw]} (phase-stable snapshot)
            const ulonglong2 p = pk[Jw];
            const int r4c = (int)(long long)p.y;
            if (lane == 0) { clist[cnt] = Jw; cdist[cnt] = minv; }
            cnt++;
            if (lane == (Jw & 31)) ms |= 1u << (Jw >> 5);   // settle: owning lane masks
            if (r4c < 0) { sink = Jw; }
            else { i = r4c; w = minv - __longlong_as_double((long long)p.x); }
        }

        __syncwarp();   // publish clist/cdist/path before cross-lane reads

        // dual updates from the compact settle list (exact JV formulas)
        for (int t = lane; t < cnt; t += 32) {
            const int    J = clist[t];
            const double d = cdist[t];
            v[J] -= minv - d;
            const int r = (int)(long long)pk[J].y;
            if (r >= 0) u[r] += minv - d;
        }
        if (lane == 0) u[cur] += minv;
        __syncwarp();

        // augment along the alternating path (lane 0)
        if (lane == 0) {
            int j = sink;
            while (true) {
                const int ii = path[j];
                row4col[j] = ii;
                const int nj = col4row[ii];
                col4row[ii] = j;
                j = nj;
                if (ii == cur) break;
            }
        }
        __syncwarp();
    }

    // ---- emit row_ind / col_ind in sorted-by-query order ----
    if (out_size >= BATCH * NQ * NT + 2 * BATCH * NT) {
        float* rows = out + (size_t)BATCH * NQ * NT;
        float* cols = rows + BATCH * NT;
        for (int t = lane; t < NT; t += 32) {
            const int q = col4row[t];
            int rank = 0;
#pragma unroll 8
            for (int tt = 0; tt < NT; tt++) rank += (col4row[tt] < q) ? 1 : 0;
            rows[b * NT + rank] = (float)q;    // row_ind: sorted query indices
            cols[b * NT + rank] = (float)t;    // col_ind: target for that query
        }
    }
}

// ---------------------------------------------------------------------------
extern "C" void kernel_launch(void* const* d_in, const int* in_sizes, int n_in,
                              void* d_out, int out_size)
{
    const float* pred_boxes = (const float*)d_in[0];   // (16, 500, 4)
    const float* pred_kpts  = (const float*)d_in[1];   // (16, 500, 17, 2)
    const float* tgt_boxes  = (const float*)d_in[2];   // (16, 128, 4)
    const float* tgt_kpts   = (const float*)d_in[3];   // (16, 128, 17, 2)
    float* out = (float*)d_out;

    dim3 cgrid(NQ / QT, BATCH);
    cost_kernel<<<cgrid, 128>>>(pred_boxes, pred_kpts, tgt_boxes, tgt_kpts, out);
    lsa_kernel<<<BATCH, 128>>>(out, out_size);
}

// round 15
// speedup vs baseline: 1.5353x; 1.0505x over previous
#include <cuda_runtime.h>
#include <math.h>

// Problem dims (fixed by the reference)
#define BATCH 16
#define NQ    500   // queries (pred) = columns
#define NT    128   // targets       = rows
#define KPT   34    // 17 keypoints * 2
#define NCPL  16    // columns per lane: ceil(500/32)
#define QT    4     // queries per cost block (500 = 125 * 4)

// Transposed cost scratch: [b][target n][query q], f32 only.
__device__ float g_ct[BATCH * NT * NQ];

// ---------------------------------------------------------------------------
// Kernel 1: cost matrix (passing R14 version, unchanged). One block per
// (b, 4 queries); targets in registers; fused transposed float4 store.
// ---------------------------------------------------------------------------
__global__ __launch_bounds__(128) void cost_kernel(
    const float* __restrict__ pred_boxes,   // (B, Q, 4)  cxcywh
    const float* __restrict__ pred_kpts,    // (B, Q, 17, 2)
    const float* __restrict__ tgt_boxes,    // (B, N, 4)  cxcywh
    const float* __restrict__ tgt_kpts,     // (B, N, 17, 2)
    float* __restrict__ C)                  // (B, Q, N)
{
    const int q0 = blockIdx.x * QT;
    const int b  = blockIdx.y;
    const int n  = threadIdx.x;

    __shared__ float s_pk[QT][KPT];
    __shared__ float s_pb[QT][4];
    for (int x = n; x < QT * KPT; x += 128)
        s_pk[x / KPT][x % KPT] = pred_kpts[(size_t)(b * NQ + q0 + x / KPT) * KPT + (x % KPT)];
    if (n < QT * 4)
        s_pb[n >> 2][n & 3] = pred_boxes[(b * NQ + q0 + (n >> 2)) * 4 + (n & 3)];
    __syncthreads();

    const float* tbn = tgt_boxes + (b * NT + n) * 4;
    const float t0 = __ldg(tbn + 0), t1 = __ldg(tbn + 1);
    const float t2 = __ldg(tbn + 2), t3 = __ldg(tbn + 3);
    float tx0 = t0 - 0.5f * t2, ty0 = t1 - 0.5f * t3;
    float tx1 = t0 + 0.5f * t2, ty1 = t1 + 0.5f * t3;
    tx1 = fmaxf(tx1, tx0 + 1e-4f);
    ty1 = fmaxf(ty1, ty0 + 1e-4f);
    const float at = (tx1 - tx0) * (ty1 - ty0);

    float tk[KPT];
    {
        const float2* tk2 = (const float2*)(tgt_kpts + (size_t)(b * NT + n) * KPT);
#pragma unroll
        for (int k = 0; k < KPT / 2; k++) {
            const float2 p = __ldg(tk2 + k);
            tk[2 * k] = p.x; tk[2 * k + 1] = p.y;
        }
    }

    float res[QT];
#pragma unroll
    for (int t = 0; t < QT; t++) {
        const float p0 = s_pb[t][0], p1 = s_pb[t][1], p2 = s_pb[t][2], p3 = s_pb[t][3];

        float cbbox = fabsf(p0 - t0) + fabsf(p1 - t1) + fabsf(p2 - t2) + fabsf(p3 - t3);

        float px0 = p0 - 0.5f * p2, py0 = p1 - 0.5f * p3;
        float px1 = p0 + 0.5f * p2, py1 = p1 + 0.5f * p3;
        px1 = fmaxf(px1, px0 + 1e-4f);
        py1 = fmaxf(py1, py0 + 1e-4f);

        const float ap = (px1 - px0) * (py1 - py0);

        const float iw = fmaxf(fminf(px1, tx1) - fmaxf(px0, tx0), 0.0f);
        const float ih = fmaxf(fminf(py1, ty1) - fmaxf(py0, ty0), 0.0f);
        const float inter = iw * ih;
        const float uni = ap + at - inter;
        const float iou = inter / uni;

        const float ew = fmaxf(fmaxf(px1, tx1) - fminf(px0, tx0), 0.0f);
        const float eh = fmaxf(fmaxf(py1, ty1) - fminf(py0, ty0), 0.0f);
        const float enc = ew * eh;
        const float giou = iou - (enc - uni) / enc;

        float ckpt = 0.0f;
#pragma unroll
        for (int k = 0; k < KPT; k++) ckpt += fabsf(s_pk[t][k] - tk[k]);

        const float cost = 5.0f * cbbox - 2.0f * giou + 1.0f * ckpt;
        res[t] = cost;
        C[(size_t)(b * NQ + q0 + t) * NT + n] = cost;
    }
    *(float4*)(g_ct + (size_t)(b * NT + n) * NQ + q0) =
        make_float4(res[0], res[1], res[2], res[3]);
}

// Monotone bijection double <-> uint64 (order-preserving, exact).
__device__ __forceinline__ unsigned long long dkey(double x) {
    const long long b = __double_as_longlong(x);
    return (unsigned long long)b ^ ((b < 0) ? 0xFFFFFFFFFFFFFFFFULL
                                             : 0x8000000000000000ULL);
}
__device__ __forceinline__ double kinv(unsigned long long k) {
    const long long b = (k & 0x8000000000000000ULL)
                      ? (long long)(k ^ 0x8000000000000000ULL)
                      : ~(long long)k;
    return __longlong_as_double(b);
}

// ---------------------------------------------------------------------------
// Kernel 2: exact JV LSA. This round: deferred-vv sweep — improve test runs
// in shifted space key(c+w) (1 DADD/column); the exact spc key (and its
// second DADD) is computed only on improvement. Argmin still on exact spc
// keys; everything else identical to passing R14.
// ---------------------------------------------------------------------------
__global__ __launch_bounds__(128) void lsa_kernel(float* __restrict__ out, int out_size)
{
    const int b    = blockIdx.x;
    const int tid  = threadIdx.x;
    const int lane = tid & 31;
    const int wid  = tid >> 5;
    const float* __restrict__ ct = g_ct + (size_t)b * NT * NQ;

    __shared__ double v[NQ];
    __shared__ double u[NT];
    __shared__ double cdist[NQ];
    __shared__ ulonglong2 pk[NQ];       // per-phase: {u[row4col[j]] bits, row4col[j]}
    __shared__ int    clist[NQ];
    __shared__ int    path[NQ];
    __shared__ int    row4col[NQ];
    __shared__ int    col4row[NT];
    __shared__ int    jmin[NT];
    __shared__ int    freelist[NT];
    __shared__ int    s_nf;

    const double DINF = __longlong_as_double(0x7FF0000000000000LL);
    const float  FINF = __int_as_float(0x7F800000);
    const unsigned FULL = 0xffffffffu;

    // ---- global init (all 128 threads) ----
    col4row[tid] = -1;
    for (int j = tid; j < NQ; j += 128) { v[j] = 0.0; row4col[j] = -1; }
    __syncthreads();

    // ---- row reduction: u[i] = min_j c[i][j] (exact in f32) ----
    for (int r = wid; r < NT; r += 4) {
        const float* __restrict__ row = ct + (size_t)r * NQ;
        float m = FINF; int mj = 0;
        for (int j = lane; j < NQ; j += 32) {
            const float c = __ldg(row + j);
            if (c < m) { m = c; mj = j; }
        }
#pragma unroll
        for (int off = 16; off > 0; off >>= 1) {
            const float ov = __shfl_down_sync(FULL, m, off);
            const int   oj = __shfl_down_sync(FULL, mj, off);
            if (ov < m || (ov == m && oj < mj)) { m = ov; mj = oj; }
        }
        if (lane == 0) { u[r] = (double)m; jmin[r] = mj; }
    }
    __syncthreads();

    // ---- greedy zero-assignment + free-row list (thread 0) ----
    if (tid == 0) {
        int nf = 0;
        for (int i = 0; i < NT; i++) {
            const int j = jmin[i];
            if (row4col[j] < 0) { row4col[j] = i; col4row[i] = j; }
            else freelist[nf++] = i;
        }
        s_nf = nf;
    }
    __syncthreads();

    if (wid != 0) return;   // warp 0 carries on alone; no __syncthreads below

    // ======== LAPJV augmenting row reduction (warp-cooperative) ========
    {
        const int nf = s_nf;
        int li = 1;
        int i = (nf > 0) ? freelist[0] : -1;
        int steps = 0;
        const int cap = 4 * nf + 8;
        while (i >= 0 && steps < cap) {
            steps++;
            const float* __restrict__ crow = ct + (size_t)i * NQ;
            double m1 = DINF, m2 = DINF;
            int j1 = -1, j2 = -1;
#pragma unroll
            for (int k = 0; k < NCPL; k++) {
                const int j = (k << 5) + lane;
                if (j < NQ) {
                    const double rc = (double)__ldg(crow + j) - v[j];
                    if (rc < m1)      { m2 = m1; j2 = j1; m1 = rc; j1 = j; }
                    else if (rc < m2) { m2 = rc; j2 = j; }
                }
            }
#pragma unroll
            for (int off = 16; off > 0; off >>= 1) {
                const double om1 = __shfl_down_sync(FULL, m1, off);
                const double om2 = __shfl_down_sync(FULL, m2, off);
                const int    oj1 = __shfl_down_sync(FULL, j1, off);
                const int    oj2 = __shfl_down_sync(FULL, j2, off);
                if (om1 < m1) {
                    if (m1 < om2) { m2 = m1;  j2 = j1;  }
                    else          { m2 = om2; j2 = oj2; }
                    m1 = om1; j1 = oj1;
                } else if (om1 < m2) { m2 = om1; j2 = oj1; }
            }
            int nexti = -1;
            if (lane == 0) {
                const double u1 = m1, u2 = m2;
                int jj = j1;
                u[i] = u2;
                if (u1 < u2)                            v[jj] -= (u2 - u1);
                else if (row4col[jj] >= 0 && j2 >= 0)   jj = j2;   // u1 == u2
                const int kk = row4col[jj];
                row4col[jj] = i; col4row[i] = jj;
                if (kk >= 0) { col4row[kk] = -1; nexti = kk; }
                else         { nexti = (li < nf) ? freelist[li++] : -1; }
            }
            nexti = __shfl_sync(FULL, nexti, 0);
            i = nexti;
            __syncwarp();
        }
    }

    // ======== Dijkstra augmenting phases (single warp, register state) ======
    for (int cur = 0; cur < NT; cur++) {
        if (col4row[cur] >= 0) continue;

        // per-phase packed snapshot (row4col and u are phase-stable)
        for (int j = lane; j < NQ; j += 32) {
            const int r = row4col[j];
            pk[j] = make_ulonglong2(
                (unsigned long long)__double_as_longlong(r >= 0 ? u[r] : 0.0),
                (unsigned long long)(long long)r);
        }
        // per-phase register caches:
        //   vv[k] : v[j] (phase-stable)
        //   kp[k] : key of the shifted value (c + w) that produced current spc
        //   ck[k] : key of the exact spc value (for the argmin)
        double vv[NCPL];
        unsigned long long kp[NCPL];
        unsigned long long ck[NCPL];
#pragma unroll
        for (int k = 0; k < NCPL; k++) {
            const int j = (k << 5) + lane;
            vv[k] = (j < NQ) ? v[j] : 0.0;
            kp[k] = ~0ULL;
            ck[k] = ~0ULL;
        }
        unsigned ms = (lane < 20) ? 0u : 0x8000u;   // k=15 invalid for lane>=20
        int cnt = 0;
        int sink = -1;
        double minv = 0.0;
        double w = -u[cur];          // first expansion: i = cur
        int i = cur;
        __syncwarp();                // pk visible

        while (sink < 0) {
            const float* __restrict__ drow = ct + (size_t)i * NQ;

            unsigned long long K0 = ~0ULL, K1 = ~0ULL, K2 = ~0ULL, K3 = ~0ULL;
            int J0 = NQ, J1 = NQ, J2 = NQ, J3 = NQ;
#pragma unroll
            for (int k = 0; k < NCPL; k++) {
                const int j = (k << 5) + lane;
                if (!((ms >> k) & 1u)) {
                    const double rp = (double)__ldg(drow + j) + w;   // 1 DADD
                    const unsigned long long keyp = dkey(rp);
                    if (keyp < kp[k]) {              // improve test, shifted space
                        kp[k] = keyp;
                        ck[k] = dkey(rp - vv[k]);    // exact spc key (2nd DADD, rare)
                        path[j] = i;
                    }
                    const unsigned long long c = ck[k];
                    switch (k & 3) {
                        case 0: if (c < K0) { K0 = c; J0 = j; } break;
                        case 1: if (c < K1) { K1 = c; J1 = j; } break;
                        case 2: if (c < K2) { K2 = c; J2 = j; } break;
                        default:if (c < K3) { K3 = c; J3 = j; } break;
                    }
                }
            }
            // merge 4 accumulators (tie -> smaller j; within each, first-min kept)
            unsigned long long K = K0; int J = J0;
            if (K1 < K || (K1 == K && J1 < J)) { K = K1; J = J1; }
            if (K2 < K || (K2 == K && J2 < J)) { K = K2; J = J2; }
            if (K3 < K || (K3 == K && J3 < J)) { K = K3; J = J3; }

            // exact 64-bit lexicographic argmin (tie -> smaller j):
            // redux on hi32, then ballot fast-path when the winner is unique.
            const unsigned hi = (unsigned)(K >> 32);
            const unsigned lo = (unsigned)K;
            const unsigned mh = __reduce_min_sync(FULL, hi);
            const unsigned bal1 = __ballot_sync(FULL, hi == mh);
            int Jw; unsigned mlv;
            if (__popc(bal1) == 1) {
                const int src = __ffs(bal1) - 1;
                Jw  = __shfl_sync(FULL, J, src);
                mlv = __shfl_sync(FULL, lo, src);
            } else {
                const unsigned ml = __reduce_min_sync(FULL, (hi == mh) ? lo : 0xffffffffu);
                const bool win = (hi == mh) && (lo == ml);
                const unsigned bal2 = __ballot_sync(FULL, win);
                if (__popc(bal2) == 1) {
                    Jw = __shfl_sync(FULL, J, __ffs(bal2) - 1);
                } else {
                    Jw = (int)__reduce_min_sync(FULL, win ? (unsigned)J : 0xffffffffu);
                }
                mlv = ml;
            }
            minv = kinv(((unsigned long long)mh << 32) | mlv);   // bit-exact spc[Jw]

            // one LDS.128: {u[row4col[Jw]], row4col[Jw]} (phase-stable snapshot)
            const ulonglong2 p = pk[Jw];
            const int r4c = (int)(long long)p.y;
            if (lane == 0) { clist[cnt] = Jw; cdist[cnt] = minv; }
            cnt++;
            if (lane == (Jw & 31)) ms |= 1u << (Jw >> 5);   // settle: owning lane masks
            if (r4c < 0) { sink = Jw; }
            else { i = r4c; w = minv - __longlong_as_double((long long)p.x); }
        }

        __syncwarp();   // publish clist/cdist/path before cross-lane reads

        // dual updates from the compact settle list (exact JV formulas)
        for (int t = lane; t < cnt; t += 32) {
            const int    J = clist[t];
            const double d = cdist[t];
            v[J] -= minv - d;
            const int r = (int)(long long)pk[J].y;
            if (r >= 0) u[r] += minv - d;
        }
        if (lane == 0) u[cur] += minv;
        __syncwarp();

        // augment along the alternating path (lane 0)
        if (lane == 0) {
            int j = sink;
            while (true) {
                const int ii = path[j];
                row4col[j] = ii;
                const int nj = col4row[ii];
                col4row[ii] = j;
                j = nj;
                if (ii == cur) break;
            }
        }
        __syncwarp();
    }

    // ---- emit row_ind / col_ind in sorted-by-query order ----
    if (out_size >= BATCH * NQ * NT + 2 * BATCH * NT) {
        float* rows = out + (size_t)BATCH * NQ * NT;
        float* cols = rows + BATCH * NT;
        for (int t = lane; t < NT; t += 32) {
            const int q = col4row[t];
            int rank = 0;
#pragma unroll 8
            for (int tt = 0; tt < NT; tt++) rank += (col4row[tt] < q) ? 1 : 0;
            rows[b * NT + rank] = (float)q;    // row_ind: sorted query indices
            cols[b * NT + rank] = (float)t;    // col_ind: target for that query
        }
    }
}

// ---------------------------------------------------------------------------
extern "C" void kernel_launch(void* const* d_in, const int* in_sizes, int n_in,
                              void* d_out, int out_size)
{
    const float* pred_boxes = (const float*)d_in[0];   // (16, 500, 4)
    const float* pred_kpts  = (const float*)d_in[1];   // (16, 500, 17, 2)
    const float* tgt_boxes  = (const float*)d_in[2];   // (16, 128, 4)
    const float* tgt_kpts   = (const float*)d_in[3];   // (16, 128, 17, 2)
    float* out = (float*)d_out;

    dim3 cgrid(NQ / QT, BATCH);
    cost_kernel<<<cgrid, 128>>>(pred_boxes, pred_kpts, tgt_boxes, tgt_kpts, out);
    lsa_kernel<<<BATCH, 128>>>(out, out_size);
}